// round 16
// baseline (speedup 1.0000x reference)
#include <cuda_runtime.h>
#include <cuda_bf16.h>
#include <math_constants.h>
#include <cstdint>

// ---------------- Problem constants ----------------
#define ROWS      19456     // B*C*N = 16*19*64
#define INPUT_DIM 200
#define NF        101       // rfft bins
#define FFTW      208       // 2*NF padded (re/im interleaved)
#define VD        64        // VQ dim
#define NCB       8192      // codebook entries

#define SZ_X      (ROWS * INPUT_DIM)
#define SZ_PROJ   (NF * VD)
#define SZ_CB     (NCB * VD)

// ---------------- Device scratch ----------------
__device__ float g_W[INPUT_DIM * FFTW];
__device__ float g_fft[ROWS * FFTW];
__device__ float g_featR[2][ROWS * VD];            // fp32 features (exact rescore)
__device__ float g_cbnR[2][NCB * VD];              // normalized codebooks fp32 (rescore)
__device__ __nv_bfloat16 g_featB[2][ROWS * VD];    // bf16 features
__device__ __nv_bfloat16 g_cbB[2][NCB * VD];       // bf16 normalized codebooks
__device__ float g_qv[2][4][ROWS];                 // per-quarter exact best value
__device__ int   g_qi[2][4][ROWS];                 // per-quarter exact best index

// ============ base-ISA asm helpers (sm_80+) ============
__device__ __forceinline__ uint32_t smem_u32(const void* p) {
    uint32_t a;
    asm("{ .reg .u64 t; cvta.to.shared.u64 t, %1; cvt.u32.u64 %0, t; }" : "=r"(a) : "l"(p));
    return a;
}
#define CP_ASYNC16(dst, src) \
    asm volatile("cp.async.ca.shared.global [%0], [%1], 16;" :: "r"(dst), "l"(src))
#define CP_COMMIT() asm volatile("cp.async.commit_group;" ::: "memory")
#define CP_WAIT(n)  asm volatile("cp.async.wait_group %0;" :: "n"(n) : "memory")
#define LDSM_X4(r, addr) \
    asm volatile("ldmatrix.sync.aligned.m8n8.x4.shared.b16 {%0,%1,%2,%3}, [%4];" \
        : "=r"((r)[0]), "=r"((r)[1]), "=r"((r)[2]), "=r"((r)[3]) : "r"(addr))
#define MMA16816(d, a, b0, b1) \
    asm volatile("mma.sync.aligned.m16n8k16.row.col.f32.bf16.bf16.f32 " \
        "{%0,%1,%2,%3}, {%4,%5,%6,%7}, {%8,%9}, {%0,%1,%2,%3};" \
        : "+f"((d)[0]), "+f"((d)[1]), "+f"((d)[2]), "+f"((d)[3]) \
        : "r"((a)[0]), "r"((a)[1]), "r"((a)[2]), "r"((a)[3]), "r"(b0), "r"(b1))

// ---------------- K0: DFT matrix (fp64 twiddles) ----------------
__global__ void build_w_kernel() {
    int i = blockIdx.x * blockDim.x + threadIdx.x;
    if (i >= INPUT_DIM * FFTW) return;
    int n = i / FFTW, c = i % FFTW, f = c >> 1;
    float val = 0.f;
    if (f < NF) {
        double s, cs;
        sincospi((double)(n * f) / 100.0, &s, &cs);
        const double scale = 0.070710678118654752440;  // 1/sqrt(200)
        val = (c & 1) ? (float)(-s * scale) : (float)(cs * scale);
    }
    g_W[i] = val;
}

// ---------------- K1: normalize codebooks -> fp32 + bf16 ----------------
__global__ void norm_cb_kernel(const float* __restrict__ cb_amp,
                               const float* __restrict__ cb_phase) {
    int which = blockIdx.y;
    const float* src = which ? cb_phase : cb_amp;
    int warp = threadIdx.x >> 5, lane = threadIdx.x & 31;
    int m = blockIdx.x * 8 + warp;
    float v0 = src[m * VD + lane];
    float v1 = src[m * VD + 32 + lane];
    float s = v0 * v0 + v1 * v1;
    #pragma unroll
    for (int o = 16; o; o >>= 1) s += __shfl_xor_sync(0xffffffffu, s, o);
    float inv = 1.f / sqrtf(s);
    float n0 = v0 * inv, n1 = v1 * inv;
    g_cbnR[which][m * VD + lane]      = n0;
    g_cbnR[which][m * VD + 32 + lane] = n1;
    g_cbB[which][m * VD + lane]      = __float2bfloat16(n0);
    g_cbB[which][m * VD + 32 + lane] = __float2bfloat16(n1);
}

// ---------------- K2: DFT GEMM (fp32 FFMA) ----------------
__global__ void dft_gemm_kernel(const float* __restrict__ x) {
    __shared__ float As[64 * 40];
    __shared__ float Bs[40 * 64];
    int tx = threadIdx.x & 15, ty = threadIdx.x >> 4;
    int rowBase = blockIdx.x * 64, colBase = blockIdx.y * 64;
    float acc[4][4] = {};
    for (int kt = 0; kt < 5; ++kt) {
        int k0 = kt * 40;
        __syncthreads();
        for (int idx = threadIdx.x; idx < 64 * 40; idx += 256) {
            int mm = idx / 40, kk = idx - mm * 40;
            As[idx] = x[(rowBase + mm) * INPUT_DIM + k0 + kk];
        }
        for (int idx = threadIdx.x; idx < 40 * 64; idx += 256) {
            int kk = idx >> 6, nn = idx & 63;
            int c = colBase + nn;
            Bs[idx] = (c < FFTW) ? g_W[(k0 + kk) * FFTW + c] : 0.f;
        }
        __syncthreads();
        #pragma unroll 8
        for (int k = 0; k < 40; ++k) {
            float4 b = *reinterpret_cast<const float4*>(&Bs[k * 64 + tx * 4]);
            float bv[4] = {b.x, b.y, b.z, b.w};
            #pragma unroll
            for (int i = 0; i < 4; ++i) {
                float a = As[(ty * 4 + i) * 40 + k];
                #pragma unroll
                for (int j = 0; j < 4; ++j) acc[i][j] += a * bv[j];
            }
        }
    }
    #pragma unroll
    for (int i = 0; i < 4; ++i) {
        int r = rowBase + ty * 4 + i;
        #pragma unroll
        for (int j = 0; j < 4; ++j) {
            int c = colBase + tx * 4 + j;
            if (c < FFTW) g_fft[r * FFTW + c] = acc[i][j];
        }
    }
}

// ---------------- K3: fused amp/phase + projection (register-blocked, transposed) ----
// 16 rows/block. pjt[d][k] stride 108 (bank-conflict-free float4), rows_s stride 108.
// Each thread: 4 rows x 1 dim, float4 over k -> 16 FMA per 5 LDS.128.
#define PR 16
#define KP 108
__global__ void proj_kernel(const float* __restrict__ proj_amp,
                            const float* __restrict__ proj_phase) {
    __shared__ float pjt[VD * KP];      // 27648B
    __shared__ float rows_s[PR * KP];   // 6912B
    int tid = threadIdx.x;
    int y = blockIdx.y;
    const float* proj = y ? proj_phase : proj_amp;
    int rowBase = blockIdx.x * PR;
    // transpose proj into pjt (coalesced read, scattered smem write)
    for (int idx = tid; idx < NF * VD; idx += 256) {
        int k = idx >> 6, d = idx & 63;
        pjt[d * KP + k] = proj[idx];
    }
    for (int idx = tid; idx < VD * (KP - NF); idx += 256) {
        int d = idx / (KP - NF), k = NF + idx % (KP - NF);
        pjt[d * KP + k] = 0.f;
    }
    // amp/phase rows
    for (int idx = tid; idx < PR * KP; idx += 256) {
        int r = idx / KP, f = idx - r * KP;
        float v = 0.f;
        if (f < NF) {
            float re = g_fft[(rowBase + r) * FFTW + 2 * f];
            float im = g_fft[(rowBase + r) * FFTW + 2 * f + 1];
            v = y ? atan2f(im, re) : sqrtf(re * re + im * im);
        }
        rows_s[idx] = v;
    }
    __syncthreads();
    int d = tid & 63, rg = tid >> 6;    // 4 rows per thread
    float acc[4] = {};
    #pragma unroll
    for (int k4 = 0; k4 < KP / 4; ++k4) {
        float4 p = *reinterpret_cast<const float4*>(&pjt[d * KP + k4 * 4]);
        #pragma unroll
        for (int rr = 0; rr < 4; ++rr) {
            float4 a = *reinterpret_cast<const float4*>(&rows_s[(rg * 4 + rr) * KP + k4 * 4]);
            acc[rr] += a.x * p.x + a.y * p.y + a.z * p.z + a.w * p.w;
        }
    }
    #pragma unroll
    for (int rr = 0; rr < 4; ++rr) {
        int row = rowBase + rg * 4 + rr;
        g_featR[y][row * VD + d] = acc[rr];
        g_featB[y][row * VD + d] = __float2bfloat16(acc[rr]);
    }
}

// ---------------- K4: HMMA bf16 score GEMM, quarter-codebook units ----
// grid (152, 2 cb, 4 quarters). BM=128, BN=64, K=64. Each quarter block sweeps
// 32 tiles, keeps per-thread top-4, exact-fp32-rescores its 32 candidates/row,
// writes per-quarter (value, index). Merge kernel finishes exactly.
#define A_STRIDE 144
#define SM_A   (128 * A_STRIDE)          // 18432
#define SM_BT  (64 * A_STRIDE)           // 9216 per buffer
#define SM_DYN (SM_A + 2 * SM_BT)        // 36864

__global__ void __launch_bounds__(256, 2)
score_kernel() {
    extern __shared__ __align__(16) unsigned char dyn[];
    const int tid = threadIdx.x;
    const int lane = tid & 31, w = tid >> 5;
    const int wm = w & 3, wn = w >> 2;
    const int g = lane >> 2, t4 = lane & 3;
    const int cb = blockIdx.y;
    const int q = blockIdx.z;
    const int rowBase = blockIdx.x * 128;
    const int tBeg = q * 32, tEnd = tBeg + 32;

    const uint32_t smA = smem_u32(dyn);
    const uint32_t smB0 = smA + SM_A;

    // ---- stage A: 128 rows x 64 bf16 -> stride 144 ----
    {
        const uint4* src = reinterpret_cast<const uint4*>(&g_featB[cb][(size_t)rowBase * VD]);
        for (int i = tid; i < 128 * 8; i += 256) {
            int r = i >> 3, c = i & 7;
            *reinterpret_cast<uint4*>(dyn + r * A_STRIDE + c * 16) = src[r * 8 + c];
        }
    }
    // ---- prefetch B tile tBeg ----
    const char* cbBp = reinterpret_cast<const char*>(g_cbB[cb]);
    {
        const char* src = cbBp + (size_t)tBeg * 64 * 128;
        for (int i = tid; i < 64 * 8; i += 256) {
            int r = i >> 3, c = i & 7;
            CP_ASYNC16(smB0 + r * A_STRIDE + c * 16, src + r * 128 + c * 16);
        }
        CP_COMMIT();
    }
    __syncthreads();

    // ---- hoist A fragments ----
    uint32_t aF[4][2][4];
    {
        uint32_t abase = smA + (wm * 32 + (lane & 15)) * A_STRIDE + ((lane >> 4) * 16);
        #pragma unroll
        for (int ks = 0; ks < 4; ++ks)
            #pragma unroll
            for (int mt = 0; mt < 2; ++mt)
                LDSM_X4(aF[ks][mt], abase + mt * 16 * A_STRIDE + ks * 32);
    }

    float tv[4][4];
    int ti[4][4];
    #pragma unroll
    for (int c = 0; c < 4; ++c)
        #pragma unroll
        for (int r = 0; r < 4; ++r) { tv[c][r] = -CUDART_INF_F; ti[c][r] = 0; }

    const uint32_t browCommon = ((((lane >> 4) & 1) * 8) + (lane & 7)) * A_STRIDE
                                + (((lane >> 3) & 1) * 16) + wn * 32 * A_STRIDE;

    for (int t = tBeg; t < tEnd; ++t) {
        if (t + 1 < tEnd) {
            const char* src = cbBp + (size_t)(t + 1) * 64 * 128;
            uint32_t base = smB0 + ((t + 1) & 1) * SM_BT;
            for (int i = tid; i < 64 * 8; i += 256) {
                int r = i >> 3, c = i & 7;
                CP_ASYNC16(base + r * A_STRIDE + c * 16, src + r * 128 + c * 16);
            }
            CP_COMMIT();
        }
        if (t < tEnd - 1) { CP_WAIT(1); } else { CP_WAIT(0); }
        __syncthreads();

        float acc[2][4][4] = {};
        const uint32_t brow = smB0 + (t & 1) * SM_BT + browCommon;
        #pragma unroll
        for (int ks = 0; ks < 4; ++ks) {
            uint32_t bF[2][4];
            #pragma unroll
            for (int p = 0; p < 2; ++p)
                LDSM_X4(bF[p], brow + p * 16 * A_STRIDE + ks * 32);
            #pragma unroll
            for (int mt = 0; mt < 2; ++mt)
                #pragma unroll
                for (int nt = 0; nt < 4; ++nt)
                    MMA16816(acc[mt][nt], aF[ks][mt],
                             bF[nt >> 1][(nt & 1) * 2], bF[nt >> 1][(nt & 1) * 2 + 1]);
        }
        __syncthreads();

        const int colb = t * 64 + wn * 32 + t4 * 2;
        #pragma unroll
        for (int mt = 0; mt < 2; ++mt)
            #pragma unroll
            for (int rh = 0; rh < 2; ++rh) {
                const int c = mt * 2 + rh;
                #pragma unroll
                for (int nt = 0; nt < 4; ++nt)
                    #pragma unroll
                    for (int e = 0; e < 2; ++e) {
                        float v = acc[mt][nt][rh * 2 + e];
                        if (v > tv[c][3]) {
                            int idx = colb + nt * 8 + e;
                            if (v > tv[c][1]) {
                                if (v > tv[c][0]) {
                                    tv[c][3] = tv[c][2]; ti[c][3] = ti[c][2];
                                    tv[c][2] = tv[c][1]; ti[c][2] = ti[c][1];
                                    tv[c][1] = tv[c][0]; ti[c][1] = ti[c][0];
                                    tv[c][0] = v; ti[c][0] = idx;
                                } else {
                                    tv[c][3] = tv[c][2]; ti[c][3] = ti[c][2];
                                    tv[c][2] = tv[c][1]; ti[c][2] = ti[c][1];
                                    tv[c][1] = v; ti[c][1] = idx;
                                }
                            } else {
                                if (v > tv[c][2]) {
                                    tv[c][3] = tv[c][2]; ti[c][3] = ti[c][2];
                                    tv[c][2] = v; ti[c][2] = idx;
                                } else {
                                    tv[c][3] = v; ti[c][3] = idx;
                                }
                            }
                        }
                    }
            }
    }

    // ---- gather 32 candidates/row (this quarter), exact fp32 rescore ----
    __syncthreads();
    int* cand = reinterpret_cast<int*>(dyn);
    #pragma unroll
    for (int c = 0; c < 4; ++c) {
        int rowl = wm * 32 + (c >> 1) * 16 + g + (c & 1) * 8;
        int slot = (wn * 4 + t4) * 4;
        #pragma unroll
        for (int r = 0; r < 4; ++r)
            cand[rowl * 32 + slot + r] = ti[c][r];
    }
    __syncthreads();
    {
        int row = tid >> 1, half = tid & 1;
        const float* fr = &g_featR[cb][(size_t)(rowBase + row) * VD];
        float fv[VD];
        #pragma unroll
        for (int k = 0; k < VD; ++k) fv[k] = fr[k];
        float bv = -CUDART_INF_F;
        int bi = NCB;
        #pragma unroll 2
        for (int s = 0; s < 16; ++s) {
            int ci = cand[row * 32 + half * 16 + s];
            const float* cr = &g_cbnR[cb][(size_t)ci * VD];
            float d = 0.f;
            #pragma unroll
            for (int k = 0; k < VD; ++k) d = fmaf(fv[k], cr[k], d);
            if (d > bv || (d == bv && ci < bi)) { bv = d; bi = ci; }
        }
        float ov = __shfl_xor_sync(0xffffffffu, bv, 1);
        int   oi = __shfl_xor_sync(0xffffffffu, bi, 1);
        if (ov > bv || (ov == bv && oi < bi)) { bv = ov; bi = oi; }
        if (half == 0) {
            g_qv[cb][q][rowBase + row] = bv;
            g_qi[cb][q][rowBase + row] = bi;
        }
    }
}

// ---------------- K5: merge 4 exact quarter-winners per row ----------------
__global__ void merge_kernel(float* __restrict__ out) {
    int i = blockIdx.x * 256 + threadIdx.x;
    if (i >= 2 * ROWS) return;
    int cb = i / ROWS, row = i - cb * ROWS;
    float bv = g_qv[cb][0][row];
    int bi = g_qi[cb][0][row];
    #pragma unroll
    for (int qq = 1; qq < 4; ++qq) {
        float v = g_qv[cb][qq][row];
        int id = g_qi[cb][qq][row];
        if (v > bv || (v == bv && id < bi)) { bv = v; bi = id; }
    }
    out[i] = (float)bi;
}

// ---------------- launch ----------------
extern "C" void kernel_launch(void* const* d_in, const int* in_sizes, int n_in,
                              void* d_out, int out_size) {
    const float* x = nullptr;
    const float* proj_amp = nullptr;
    const float* proj_phase = nullptr;
    const float* cb_amp = nullptr;
    const float* cb_phase = nullptr;
    for (int i = 0; i < n_in; ++i) {
        const float* p = (const float*)d_in[i];
        int sz = in_sizes[i];
        if (sz == SZ_X) x = p;
        else if (sz == SZ_PROJ) { if (!proj_amp) proj_amp = p; else proj_phase = p; }
        else if (sz == SZ_CB)   { if (!cb_amp)   cb_amp = p;   else cb_phase = p; }
    }
    float* out = (float*)d_out;

    build_w_kernel<<<(INPUT_DIM * FFTW + 255) / 256, 256>>>();
    norm_cb_kernel<<<dim3(NCB / 8, 2), 256>>>(cb_amp, cb_phase);
    dft_gemm_kernel<<<dim3(ROWS / 64, 4), 256>>>(x);
    proj_kernel<<<dim3(ROWS / PR, 2), 256>>>(proj_amp, proj_phase);
    score_kernel<<<dim3(ROWS / 128, 2, 4), 256, SM_DYN>>>();
    merge_kernel<<<(2 * ROWS + 255) / 256, 256>>>(out);
}

// round 17
// speedup vs baseline: 2.2176x; 2.2176x over previous
#include <cuda_runtime.h>
#include <cuda_bf16.h>
#include <math_constants.h>
#include <cstdint>

// ---------------- Problem constants ----------------
#define ROWS      19456     // B*C*N = 16*19*64
#define INPUT_DIM 200
#define NF        101       // rfft bins
#define FFTW      208       // 2*NF padded (re/im interleaved)
#define VD        64        // VQ dim
#define NCB       8192      // codebook entries

#define SZ_X      (ROWS * INPUT_DIM)
#define SZ_PROJ   (NF * VD)
#define SZ_CB     (NCB * VD)

// ---------------- Device scratch ----------------
__device__ float g_W[INPUT_DIM * FFTW];
__device__ float g_fft[ROWS * FFTW];
__device__ float g_featR[2][ROWS * VD];            // fp32 features (exact rescore)
__device__ float g_cbnR[2][NCB * VD];              // normalized codebooks fp32 (rescore)
__device__ __nv_bfloat16 g_featB[2][ROWS * VD];    // bf16 features
__device__ __nv_bfloat16 g_cbB[2][NCB * VD];       // bf16 normalized codebooks

// ============ base-ISA asm helpers (sm_80+) ============
__device__ __forceinline__ uint32_t smem_u32(const void* p) {
    uint32_t a;
    asm("{ .reg .u64 t; cvta.to.shared.u64 t, %1; cvt.u32.u64 %0, t; }" : "=r"(a) : "l"(p));
    return a;
}
#define CP_ASYNC16(dst, src) \
    asm volatile("cp.async.ca.shared.global [%0], [%1], 16;" :: "r"(dst), "l"(src))
#define CP_COMMIT() asm volatile("cp.async.commit_group;" ::: "memory")
#define CP_WAIT(n)  asm volatile("cp.async.wait_group %0;" :: "n"(n) : "memory")
#define LDSM_X4(r, addr) \
    asm volatile("ldmatrix.sync.aligned.m8n8.x4.shared.b16 {%0,%1,%2,%3}, [%4];" \
        : "=r"((r)[0]), "=r"((r)[1]), "=r"((r)[2]), "=r"((r)[3]) : "r"(addr))
#define MMA16816(d, a, b0, b1) \
    asm volatile("mma.sync.aligned.m16n8k16.row.col.f32.bf16.bf16.f32 " \
        "{%0,%1,%2,%3}, {%4,%5,%6,%7}, {%8,%9}, {%0,%1,%2,%3};" \
        : "+f"((d)[0]), "+f"((d)[1]), "+f"((d)[2]), "+f"((d)[3]) \
        : "r"((a)[0]), "r"((a)[1]), "r"((a)[2]), "r"((a)[3]), "r"(b0), "r"(b1))

// ---------------- K1: fused init — DFT matrix + codebook normalize ----------------
// grid (1187, 2): x<1024 -> normalize codebook y; x>=1024 (y==0 only) -> build W.
__global__ void init_kernel(const float* __restrict__ cb_amp,
                            const float* __restrict__ cb_phase) {
    if (blockIdx.x < 1024) {
        int which = blockIdx.y;
        const float* src = which ? cb_phase : cb_amp;
        int warp = threadIdx.x >> 5, lane = threadIdx.x & 31;
        int m = blockIdx.x * 8 + warp;
        float v0 = src[m * VD + lane];
        float v1 = src[m * VD + 32 + lane];
        float s = v0 * v0 + v1 * v1;
        #pragma unroll
        for (int o = 16; o; o >>= 1) s += __shfl_xor_sync(0xffffffffu, s, o);
        float inv = 1.f / sqrtf(s);
        float n0 = v0 * inv, n1 = v1 * inv;
        g_cbnR[which][m * VD + lane]      = n0;
        g_cbnR[which][m * VD + 32 + lane] = n1;
        g_cbB[which][m * VD + lane]      = __float2bfloat16(n0);
        g_cbB[which][m * VD + 32 + lane] = __float2bfloat16(n1);
    } else if (blockIdx.y == 0) {
        int i = (blockIdx.x - 1024) * blockDim.x + threadIdx.x;
        if (i >= INPUT_DIM * FFTW) return;
        int n = i / FFTW, c = i % FFTW, f = c >> 1;
        float val = 0.f;
        if (f < NF) {
            double s, cs;
            sincospi((double)(n * f) / 100.0, &s, &cs);
            const double scale = 0.070710678118654752440;  // 1/sqrt(200)
            val = (c & 1) ? (float)(-s * scale) : (float)(cs * scale);
        }
        g_W[i] = val;
    }
}

// ---------------- K2: DFT GEMM (fp32 FFMA) ----------------
__global__ void dft_gemm_kernel(const float* __restrict__ x) {
    __shared__ float As[64 * 40];
    __shared__ float Bs[40 * 64];
    int tx = threadIdx.x & 15, ty = threadIdx.x >> 4;
    int rowBase = blockIdx.x * 64, colBase = blockIdx.y * 64;
    float acc[4][4] = {};
    for (int kt = 0; kt < 5; ++kt) {
        int k0 = kt * 40;
        __syncthreads();
        for (int idx = threadIdx.x; idx < 64 * 40; idx += 256) {
            int mm = idx / 40, kk = idx - mm * 40;
            As[idx] = x[(rowBase + mm) * INPUT_DIM + k0 + kk];
        }
        for (int idx = threadIdx.x; idx < 40 * 64; idx += 256) {
            int kk = idx >> 6, nn = idx & 63;
            int c = colBase + nn;
            Bs[idx] = (c < FFTW) ? g_W[(k0 + kk) * FFTW + c] : 0.f;
        }
        __syncthreads();
        #pragma unroll 8
        for (int k = 0; k < 40; ++k) {
            float4 b = *reinterpret_cast<const float4*>(&Bs[k * 64 + tx * 4]);
            float bv[4] = {b.x, b.y, b.z, b.w};
            #pragma unroll
            for (int i = 0; i < 4; ++i) {
                float a = As[(ty * 4 + i) * 40 + k];
                #pragma unroll
                for (int j = 0; j < 4; ++j) acc[i][j] += a * bv[j];
            }
        }
    }
    #pragma unroll
    for (int i = 0; i < 4; ++i) {
        int r = rowBase + ty * 4 + i;
        #pragma unroll
        for (int j = 0; j < 4; ++j) {
            int c = colBase + tx * 4 + j;
            if (c < FFTW) g_fft[r * FFTW + c] = acc[i][j];
        }
    }
}

// ---------------- K3: fused amp/phase + projection (register-blocked, transposed) ----
#define PR 16
#define KP 108
__global__ void proj_kernel(const float* __restrict__ proj_amp,
                            const float* __restrict__ proj_phase) {
    __shared__ float pjt[VD * KP];      // 27648B
    __shared__ float rows_s[PR * KP];   // 6912B
    int tid = threadIdx.x;
    int y = blockIdx.y;
    const float* proj = y ? proj_phase : proj_amp;
    int rowBase = blockIdx.x * PR;
    for (int idx = tid; idx < NF * VD; idx += 256) {
        int k = idx >> 6, d = idx & 63;
        pjt[d * KP + k] = proj[idx];
    }
    for (int idx = tid; idx < VD * (KP - NF); idx += 256) {
        int d = idx / (KP - NF), k = NF + idx % (KP - NF);
        pjt[d * KP + k] = 0.f;
    }
    for (int idx = tid; idx < PR * KP; idx += 256) {
        int r = idx / KP, f = idx - r * KP;
        float v = 0.f;
        if (f < NF) {
            float re = g_fft[(rowBase + r) * FFTW + 2 * f];
            float im = g_fft[(rowBase + r) * FFTW + 2 * f + 1];
            v = y ? atan2f(im, re) : sqrtf(re * re + im * im);
        }
        rows_s[idx] = v;
    }
    __syncthreads();
    int d = tid & 63, rg = tid >> 6;    // 4 rows per thread
    float acc[4] = {};
    #pragma unroll
    for (int k4 = 0; k4 < KP / 4; ++k4) {
        float4 p = *reinterpret_cast<const float4*>(&pjt[d * KP + k4 * 4]);
        #pragma unroll
        for (int rr = 0; rr < 4; ++rr) {
            float4 a = *reinterpret_cast<const float4*>(&rows_s[(rg * 4 + rr) * KP + k4 * 4]);
            acc[rr] += a.x * p.x + a.y * p.y + a.z * p.z + a.w * p.w;
        }
    }
    #pragma unroll
    for (int rr = 0; rr < 4; ++rr) {
        int row = rowBase + rg * 4 + rr;
        g_featR[y][row * VD + d] = acc[rr];
        g_featB[y][row * VD + d] = __float2bfloat16(acc[rr]);
    }
}

// ---------------- K4: HMMA bf16 score GEMM + per-thread top4 + exact fp32 rescore ----
// (Proven R15 version: 495us, rel_err 0.0.) BM=128, BN=64, K=64. 8 warps 4x2.
#define A_STRIDE 144
#define SM_A   (128 * A_STRIDE)          // 18432
#define SM_BT  (64 * A_STRIDE)           // 9216 per buffer
#define SM_DYN (SM_A + 2 * SM_BT)        // 36864

__global__ void __launch_bounds__(256, 2)
score_kernel(float* __restrict__ out) {
    extern __shared__ __align__(16) unsigned char dyn[];
    const int tid = threadIdx.x;
    const int lane = tid & 31, w = tid >> 5;
    const int wm = w & 3, wn = w >> 2;
    const int g = lane >> 2, t4 = lane & 3;
    const int cb = blockIdx.y;
    const int rowBase = blockIdx.x * 128;

    const uint32_t smA = smem_u32(dyn);
    const uint32_t smB0 = smA + SM_A;

    {
        const uint4* src = reinterpret_cast<const uint4*>(&g_featB[cb][(size_t)rowBase * VD]);
        for (int i = tid; i < 128 * 8; i += 256) {
            int r = i >> 3, c = i & 7;
            *reinterpret_cast<uint4*>(dyn + r * A_STRIDE + c * 16) = src[r * 8 + c];
        }
    }
    const char* cbBp = reinterpret_cast<const char*>(g_cbB[cb]);
    {
        for (int i = tid; i < 64 * 8; i += 256) {
            int r = i >> 3, c = i & 7;
            CP_ASYNC16(smB0 + r * A_STRIDE + c * 16, cbBp + r * 128 + c * 16);
        }
        CP_COMMIT();
    }
    __syncthreads();

    uint32_t aF[4][2][4];
    {
        uint32_t abase = smA + (wm * 32 + (lane & 15)) * A_STRIDE + ((lane >> 4) * 16);
        #pragma unroll
        for (int ks = 0; ks < 4; ++ks)
            #pragma unroll
            for (int mt = 0; mt < 2; ++mt)
                LDSM_X4(aF[ks][mt], abase + mt * 16 * A_STRIDE + ks * 32);
    }

    float tv[4][4];
    int ti[4][4];
    #pragma unroll
    for (int c = 0; c < 4; ++c)
        #pragma unroll
        for (int r = 0; r < 4; ++r) { tv[c][r] = -CUDART_INF_F; ti[c][r] = 0; }

    const uint32_t browCommon = ((((lane >> 4) & 1) * 8) + (lane & 7)) * A_STRIDE
                                + (((lane >> 3) & 1) * 16) + wn * 32 * A_STRIDE;

    for (int t = 0; t < 128; ++t) {
        if (t + 1 < 128) {
            const char* src = cbBp + (size_t)(t + 1) * 64 * 128;
            uint32_t base = smB0 + ((t + 1) & 1) * SM_BT;
            for (int i = tid; i < 64 * 8; i += 256) {
                int r = i >> 3, c = i & 7;
                CP_ASYNC16(base + r * A_STRIDE + c * 16, src + r * 128 + c * 16);
            }
            CP_COMMIT();
        }
        if (t < 127) { CP_WAIT(1); } else { CP_WAIT(0); }
        __syncthreads();

        float acc[2][4][4] = {};
        const uint32_t brow = smB0 + (t & 1) * SM_BT + browCommon;
        #pragma unroll
        for (int ks = 0; ks < 4; ++ks) {
            uint32_t bF[2][4];
            #pragma unroll
            for (int p = 0; p < 2; ++p)
                LDSM_X4(bF[p], brow + p * 16 * A_STRIDE + ks * 32);
            #pragma unroll
            for (int mt = 0; mt < 2; ++mt)
                #pragma unroll
                for (int nt = 0; nt < 4; ++nt)
                    MMA16816(acc[mt][nt], aF[ks][mt],
                             bF[nt >> 1][(nt & 1) * 2], bF[nt >> 1][(nt & 1) * 2 + 1]);
        }
        __syncthreads();

        const int colb = t * 64 + wn * 32 + t4 * 2;
        #pragma unroll
        for (int mt = 0; mt < 2; ++mt)
            #pragma unroll
            for (int rh = 0; rh < 2; ++rh) {
                const int c = mt * 2 + rh;
                #pragma unroll
                for (int nt = 0; nt < 4; ++nt)
                    #pragma unroll
                    for (int e = 0; e < 2; ++e) {
                        float v = acc[mt][nt][rh * 2 + e];
                        if (v > tv[c][3]) {
                            int idx = colb + nt * 8 + e;
                            if (v > tv[c][1]) {
                                if (v > tv[c][0]) {
                                    tv[c][3] = tv[c][2]; ti[c][3] = ti[c][2];
                                    tv[c][2] = tv[c][1]; ti[c][2] = ti[c][1];
                                    tv[c][1] = tv[c][0]; ti[c][1] = ti[c][0];
                                    tv[c][0] = v; ti[c][0] = idx;
                                } else {
                                    tv[c][3] = tv[c][2]; ti[c][3] = ti[c][2];
                                    tv[c][2] = tv[c][1]; ti[c][2] = ti[c][1];
                                    tv[c][1] = v; ti[c][1] = idx;
                                }
                            } else {
                                if (v > tv[c][2]) {
                                    tv[c][3] = tv[c][2]; ti[c][3] = ti[c][2];
                                    tv[c][2] = v; ti[c][2] = idx;
                                } else {
                                    tv[c][3] = v; ti[c][3] = idx;
                                }
                            }
                        }
                    }
            }
    }

    // ---- gather 32 candidates/row, exact fp32 rescore (2 threads per row) ----
    __syncthreads();
    int* cand = reinterpret_cast<int*>(dyn);
    #pragma unroll
    for (int c = 0; c < 4; ++c) {
        int rowl = wm * 32 + (c >> 1) * 16 + g + (c & 1) * 8;
        int slot = (wn * 4 + t4) * 4;
        #pragma unroll
        for (int r = 0; r < 4; ++r)
            cand[rowl * 32 + slot + r] = ti[c][r];
    }
    __syncthreads();
    {
        int row = tid >> 1, half = tid & 1;
        const float* fr = &g_featR[cb][(size_t)(rowBase + row) * VD];
        float fv[VD];
        #pragma unroll
        for (int k = 0; k < VD; ++k) fv[k] = fr[k];
        float bv = -CUDART_INF_F;
        int bi = NCB;
        #pragma unroll 2
        for (int s = 0; s < 16; ++s) {
            int ci = cand[row * 32 + half * 16 + s];
            const float* cr = &g_cbnR[cb][(size_t)ci * VD];
            float d = 0.f;
            #pragma unroll
            for (int k = 0; k < VD; ++k) d = fmaf(fv[k], cr[k], d);
            if (d > bv || (d == bv && ci < bi)) { bv = d; bi = ci; }
        }
        float ov = __shfl_xor_sync(0xffffffffu, bv, 1);
        int   oi = __shfl_xor_sync(0xffffffffu, bi, 1);
        if (ov > bv || (ov == bv && oi < bi)) { bv = ov; bi = oi; }
        if (half == 0) out[cb * ROWS + rowBase + row] = (float)bi;
    }
}

// ---------------- launch ----------------
extern "C" void kernel_launch(void* const* d_in, const int* in_sizes, int n_in,
                              void* d_out, int out_size) {
    const float* x = nullptr;
    const float* proj_amp = nullptr;
    const float* proj_phase = nullptr;
    const float* cb_amp = nullptr;
    const float* cb_phase = nullptr;
    for (int i = 0; i < n_in; ++i) {
        const float* p = (const float*)d_in[i];
        int sz = in_sizes[i];
        if (sz == SZ_X) x = p;
        else if (sz == SZ_PROJ) { if (!proj_amp) proj_amp = p; else proj_phase = p; }
        else if (sz == SZ_CB)   { if (!cb_amp)   cb_amp = p;   else cb_phase = p; }
    }
    float* out = (float*)d_out;

    // 4 launches: score_kernel is the 4th -> lands in the ncu capture window.
    init_kernel<<<dim3(1187, 2), 256>>>(cb_amp, cb_phase);
    dft_gemm_kernel<<<dim3(ROWS / 64, 4), 256>>>(x);
    proj_kernel<<<dim3(ROWS / PR, 2), 256>>>(proj_amp, proj_phase);
    score_kernel<<<dim3(ROWS / 128, 2), 256, SM_DYN>>>(out);
}